// round 10
// baseline (speedup 1.0000x reference)
#include <cuda_runtime.h>
#include <math.h>

#define IMG_H 28
#define IMG_W 28
#define IMG_N 784
#define SWIN  11
#define SOUT  18        // 28-11+1
#define HPAD  19        // padded row stride for Huv/Hpq
#define C_IMG 32        // images per block chunk

typedef unsigned long long u64;

// persistent accumulators; reset by the finalizing block each launch
__device__ double   g_acc[7 * 64];                 // zero-init at load
__device__ unsigned g_minenc = 0xFFFFFFFFu;
__device__ unsigned g_maxenc = 0u;
__device__ unsigned g_done   = 0u;
__device__ float    g_gw[SWIN];

// ---- float ordering encode/decode for atomic min/max ----
__device__ __forceinline__ unsigned encf(float f) {
    unsigned u = __float_as_uint(f);
    return (u & 0x80000000u) ? ~u : (u | 0x80000000u);
}
__device__ __forceinline__ float decf(unsigned e) {
    unsigned u = (e & 0x80000000u) ? (e & 0x7FFFFFFFu) : ~e;
    return __uint_as_float(u);
}

// ---- packed f32x2 helpers ----
__device__ __forceinline__ u64 pack2(float x, float y) {
    u64 r;
    asm("mov.b64 %0, {%1, %2};" : "=l"(r) : "r"(__float_as_uint(x)), "r"(__float_as_uint(y)));
    return r;
}
__device__ __forceinline__ void unpack2(u64 v, float &x, float &y) {
    unsigned a, b;
    asm("mov.b64 {%0, %1}, %2;" : "=r"(a), "=r"(b) : "l"(v));
    x = __uint_as_float(a);
    y = __uint_as_float(b);
}
__device__ __forceinline__ u64 fma2(u64 a, u64 b, u64 c) {   // a*b + c
    u64 d;
    asm("fma.rn.f32x2 %0, %1, %2, %3;" : "=l"(d) : "l"(a), "l"(b), "l"(c));
    return d;
}
__device__ __forceinline__ u64 add2(u64 a, u64 b) {
    u64 d;
    asm("add.rn.f32x2 %0, %1, %2;" : "=l"(d) : "l"(a), "l"(b));
    return d;
}
__device__ __forceinline__ u64 mul2(u64 a, u64 b) {
    u64 d;
    asm("mul.rn.f32x2 %0, %1, %2;" : "=l"(d) : "l"(a), "l"(b));
    return d;
}

// ================= min/max of target (+ one-time per-launch setup) =======
__global__ __launch_bounds__(256) void k_minmax(const float4* __restrict__ t, int n4) {
    if (blockIdx.x == 0 && threadIdx.x == 0) {
        // no race: k_fused (stream-ordered after this kernel) is the only reader
        double w[SWIN], s = 0.0;
        for (int i = 0; i < SWIN; i++) {
            double c = (double)i - (SWIN / 2);
            w[i] = exp(-(c * c) / (2.0 * 1.5 * 1.5));
            s += w[i];
        }
        for (int i = 0; i < SWIN; i++) g_gw[i] = (float)(w[i] / s);
    }
    float lo0 = 3.402823466e38f, hi0 = -3.402823466e38f;
    float lo1 = lo0, hi1 = hi0;
    int stride = gridDim.x * blockDim.x;
    for (int i = blockIdx.x * blockDim.x + threadIdx.x; i < n4; i += 2 * stride) {
        float4 x = t[i];
        lo0 = fminf(lo0, fminf(fminf(x.x, x.y), fminf(x.z, x.w)));
        hi0 = fmaxf(hi0, fmaxf(fmaxf(x.x, x.y), fmaxf(x.z, x.w)));
        int j = i + stride;
        if (j < n4) {
            float4 y = t[j];
            lo1 = fminf(lo1, fminf(fminf(y.x, y.y), fminf(y.z, y.w)));
            hi1 = fmaxf(hi1, fmaxf(fmaxf(y.x, y.y), fmaxf(y.z, y.w)));
        }
    }
    float lo = fminf(lo0, lo1), hi = fmaxf(hi0, hi1);
#pragma unroll
    for (int o = 16; o; o >>= 1) {
        lo = fminf(lo, __shfl_down_sync(0xFFFFFFFFu, lo, o));
        hi = fmaxf(hi, __shfl_down_sync(0xFFFFFFFFu, hi, o));
    }
    if ((threadIdx.x & 31) == 0) {
        atomicMin(&g_minenc, encf(lo));
        atomicMax(&g_maxenc, encf(hi));
    }
}

// ========== fused: MSE + SSIM + sobel + batch-smooth + Pearson + final ====
__global__ __launch_bounds__(256) void k_fused(const float4* __restrict__ o4,
                                               const float4* __restrict__ t4,
                                               float* __restrict__ out,
                                               int out_size, int B) {
    __shared__ u64 uv[IMG_N];            // (u=o+t, v=o-t) packed
    __shared__ u64 gsm[IMG_N];           // sobel (smu, smv) of current image
    __shared__ u64 Huv[IMG_H * HPAD];    // horiz-filtered (U,V)
    __shared__ u64 Hpq[IMG_H * HPAD];    // horiz-filtered (P,Q)
    __shared__ float red[8][7];
    __shared__ int isLast;
    __shared__ double fs[7];

    const int tid = threadIdx.x;
    const int c0 = blockIdx.x * C_IMG;

    // Gaussian weights, symmetric: keep 6, map k -> min(k, 10-k)
    u64 ww[6];
#pragma unroll
    for (int k = 0; k < 6; k++) { float w = g_gw[k]; ww[k] = pack2(w, w); }
    const u64 TWO2 = pack2(2.0f, 2.0f);
    const u64 NEG1 = pack2(-1.0f, -1.0f);

    float R  = decf(g_maxenc) - decf(g_minenc);
    float C1 = (0.01f * R) * (0.01f * R);
    float C2 = (0.03f * R) * (0.03f * R);

    // per-thread accumulators
    float msep = 0.f, ssimp = 0.f;
    float Sa = 0.f, Sb = 0.f, Saa = 0.f, Sbb = 0.f, Sab = 0.f;

    // Pearson batch-recurrence registers: pixels p = tid + 256*k
    u64 gm[4], gc[4];
#pragma unroll
    for (int k = 0; k < 4; k++) { gm[k] = 0; gc[k] = 0; }

#pragma unroll 1
    for (int ii = -1; ii <= C_IMG; ii++) {
        int b = c0 + ii;
        int bc = b < 0 ? 0 : (b >= B ? B - 1 : b);
        const bool interior = (ii >= 0) && (ii < C_IMG);

        // ---------- phase A: load image bc, build uv (+mse if interior)
        if (tid < IMG_N / 4) {
            const float4* ob = o4 + (size_t)bc * (IMG_N / 4);
            const float4* tb = t4 + (size_t)bc * (IMG_N / 4);
            float4 a = ob[tid], c = tb[tid];
            float v0 = a.x - c.x, v1 = a.y - c.y;
            float v2 = a.z - c.z, v3 = a.w - c.w;
            int base = tid * 4;
            uv[base + 0] = pack2(a.x + c.x, v0);
            uv[base + 1] = pack2(a.y + c.y, v1);
            uv[base + 2] = pack2(a.z + c.z, v2);
            uv[base + 3] = pack2(a.w + c.w, v3);
            if (interior)
                msep += v0 * v0 + v1 * v1 + v2 * v2 + v3 * v3;
        }
        __syncthreads();

        // ---------- phase B: horiz conv (tid<168, warps 0-5) + sobel (192..247)
        if (tid < 168) {
            if (interior) {
                int r = tid / 6, seg = tid - 6 * (tid / 6);
                int j0 = seg * 3;
                int ibase = r * IMG_W + j0;
                u64 au[3], ap[3];
#pragma unroll
                for (int oi = 0; oi < 3; oi++) { au[oi] = 0; ap[oi] = 0; }
#pragma unroll
                for (int t = 0; t < 13; t++) {
                    u64 xu = uv[ibase + t];
                    u64 xp = mul2(xu, xu);
#pragma unroll
                    for (int oi = 0; oi < 3; oi++) {
                        int k = t - oi;
                        if (k >= 0 && k < SWIN) {
                            int kk = (k < 6) ? k : 10 - k;
                            au[oi] = fma2(ww[kk], xu, au[oi]);
                            ap[oi] = fma2(ww[kk], xp, ap[oi]);
                        }
                    }
                }
                int obase = r * HPAD + j0;
#pragma unroll
                for (int oi = 0; oi < 3; oi++) {
                    Huv[obase + oi] = au[oi];
                    Hpq[obase + oi] = ap[oi];
                }
            }
        } else if (tid >= 192 && tid < 248) {
            int s = tid - 192;              // 0..55, warps 6-7 only
            int c = s >> 1, half = s & 1;
            int cp = (c < IMG_W - 1) ? c + 1 : IMG_W - 1;
            int cm = (c > 0) ? c - 1 : 0;
            int r0 = half * 14;
            int rm0 = (r0 > 0) ? r0 - 1 : 0;
            u64 dm = fma2(NEG1, uv[rm0 * IMG_W + cm], uv[rm0 * IMG_W + cp]);
            u64 dc = fma2(NEG1, uv[r0 * IMG_W + cm], uv[r0 * IMG_W + cp]);
#pragma unroll
            for (int rr = 0; rr < 14; rr++) {
                int r = r0 + rr;
                int rp = (r < IMG_H - 1) ? r + 1 : IMG_H - 1;
                u64 dp = fma2(NEG1, uv[rp * IMG_W + cm], uv[rp * IMG_W + cp]);
                gsm[r * IMG_W + c] = fma2(TWO2, dc, add2(dm, dp));   // (smu,smv)
                dm = dc; dc = dp;
            }
        }
        __syncthreads();

        // ---------- phase C: vert conv + SSIM (tid<108, interior); Pearson (all)
        if (interior && tid < 108) {
            int cc = tid / 6, seg = tid - 6 * (tid / 6);
            int j0 = seg * 3;
            u64 au[3], ap[3];
#pragma unroll
            for (int oi = 0; oi < 3; oi++) { au[oi] = 0; ap[oi] = 0; }
#pragma unroll
            for (int t = 0; t < 13; t++) {
                u64 xu = Huv[(j0 + t) * HPAD + cc];
                u64 xp = Hpq[(j0 + t) * HPAD + cc];
#pragma unroll
                for (int oi = 0; oi < 3; oi++) {
                    int k = t - oi;
                    if (k >= 0 && k < SWIN) {
                        int kk = (k < 6) ? k : 10 - k;
                        au[oi] = fma2(ww[kk], xu, au[oi]);
                        ap[oi] = fma2(ww[kk], xp, ap[oi]);
                    }
                }
            }
#pragma unroll
            for (int oi = 0; oi < 3; oi++) {
                float U, V, P, Q;
                unpack2(au[oi], U, V);
                unpack2(ap[oi], P, Q);
                float A = U * U, Bv = V * V;
                float num1 = 0.5f * (A - Bv) + C1;           // 2*mu1mu2 + C1
                float den1 = 0.5f * (A + Bv) + C1;           // mu1^2+mu2^2 + C1
                float num2 = 0.5f * (P - Q - A + Bv) + C2;   // 2*s12 + C2
                float den2 = 0.5f * (P + Q - A - Bv) + C2;   // s1+s2 + C2
                ssimp += __fdividef(num1 * num2, den1 * den2);
            }
        }

        // Pearson batch recurrence: s[jp] = g[jp-1] + 2 g[jp] + g[jp+1], jp=ii-1
#pragma unroll
        for (int k = 0; k < 4; k++) {
            int p = tid + k * 256;
            if (p < IMG_N) {
                u64 gn = gsm[p];
                if (ii >= 1) {
                    u64 t1 = fma2(TWO2, gc[k], add2(gm[k], gn));
                    float su, sv;
                    unpack2(t1, su, sv);
                    float sa = su + sv, sb = su - sv;   // scale cancels in pearson
                    Sa += sa; Sb += sb;
                    Saa = fmaf(sa, sa, Saa);
                    Sbb = fmaf(sb, sb, Sbb);
                    Sab = fmaf(sa, sb, Sab);
                }
                gm[k] = gc[k]; gc[k] = gn;
            }
        }
        // no sync needed here: next phase A writes only uv (not read in phase C),
        // and the sync after A orders gsm/Huv rewrites.
    }

    // ---------- block reduction: 7 sums ----------
    float v0 = msep, v1 = ssimp, v2 = Sa, v3 = Sb, v4 = Saa, v5 = Sbb, v6 = Sab;
#pragma unroll
    for (int o = 16; o; o >>= 1) {
        v0 += __shfl_down_sync(0xFFFFFFFFu, v0, o);
        v1 += __shfl_down_sync(0xFFFFFFFFu, v1, o);
        v2 += __shfl_down_sync(0xFFFFFFFFu, v2, o);
        v3 += __shfl_down_sync(0xFFFFFFFFu, v3, o);
        v4 += __shfl_down_sync(0xFFFFFFFFu, v4, o);
        v5 += __shfl_down_sync(0xFFFFFFFFu, v5, o);
        v6 += __shfl_down_sync(0xFFFFFFFFu, v6, o);
    }
    int wid = tid >> 5;
    if ((tid & 31) == 0) {
        red[wid][0] = v0; red[wid][1] = v1; red[wid][2] = v2; red[wid][3] = v3;
        red[wid][4] = v4; red[wid][5] = v5; red[wid][6] = v6;
    }
    __syncthreads();
    if (tid < 7) {
        double s = 0;
        for (int w = 0; w < 8; w++) s += (double)red[w][tid];
        atomicAdd(&g_acc[tid * 64 + (blockIdx.x & 63)], s);
    }

    // ---------- last-block finalize + state reset ----------
    if (tid == 0) {
        __threadfence();
        unsigned prev = atomicAdd(&g_done, 1u);
        isLast = (prev == gridDim.x - 1) ? 1 : 0;
    }
    __syncthreads();
    if (isLast) {
        __threadfence();   // acquire: all blocks' g_acc writes visible
        if (tid < 7) fs[tid] = 0.0;
        __syncthreads();
        for (int i = tid; i < 7 * 64; i += 256) atomicAdd(&fs[i >> 6], g_acc[i]);
        __syncthreads();
        if (tid == 0) {
            double N    = (double)B * (double)IMG_N;
            double mse  = fs[0] / N;
            double ssim = fs[1] / ((double)B * (double)(SOUT * SOUT));
            double psnr = 10.0 * log10(1.0 / mse);
            double SA = fs[2], SB = fs[3], SAA = fs[4], SBB = fs[5], SAB = fs[6];
            double num = SAB - SA * SB / N;
            double den = sqrt((SAA - SA * SA / N) * (SBB - SB * SB / N));
            double epi = num / den;
            double loss = 1.0 * mse + 0.5 * (1.0 - ssim) + 0.1 * epi + 0.01 * psnr;
            for (int i = 0; i < out_size; i++) out[i] = (float)loss;
        }
        // reset persistent state for the next graph replay
        for (int i = tid; i < 7 * 64; i += 256) g_acc[i] = 0.0;
        if (tid == 1) { g_minenc = 0xFFFFFFFFu; g_maxenc = 0u; }
        if (tid == 2) g_done = 0u;
    }
}

// ================= launcher =================
extern "C" void kernel_launch(void* const* d_in, const int* in_sizes, int n_in,
                              void* d_out, int out_size) {
    const float4* o4 = (const float4*)d_in[0];  // "output"
    const float4* t4 = (const float4*)d_in[1];  // "target"
    int n = in_sizes[0];
    int B = n / IMG_N;           // 65536

    k_minmax<<<2048, 256>>>(t4, n / 4);
    k_fused<<<B / C_IMG, 256>>>(o4, t4, (float*)d_out, out_size, B);
}

// round 11
// speedup vs baseline: 1.5801x; 1.5801x over previous
#include <cuda_runtime.h>
#include <math.h>

#define IMG_H 28
#define IMG_W 28
#define IMG_N 784
#define SWIN  11
#define SOUT  18        // 28-11+1
#define HPAD  19        // padded row stride for Huv/Hpq
#define C_IMG 16        // images per block chunk

typedef unsigned long long u64;

// persistent accumulators; reset by the finalizing block each launch
__device__ double   g_acc[7 * 64];                 // zero-init at load
__device__ unsigned g_minenc = 0xFFFFFFFFu;
__device__ unsigned g_maxenc = 0u;
__device__ unsigned g_done   = 0u;
__device__ float    g_gw[SWIN];

// ---- float ordering encode/decode for atomic min/max ----
__device__ __forceinline__ unsigned encf(float f) {
    unsigned u = __float_as_uint(f);
    return (u & 0x80000000u) ? ~u : (u | 0x80000000u);
}
__device__ __forceinline__ float decf(unsigned e) {
    unsigned u = (e & 0x80000000u) ? (e & 0x7FFFFFFFu) : ~e;
    return __uint_as_float(u);
}

// ---- packed f32x2 helpers ----
__device__ __forceinline__ u64 pack2(float x, float y) {
    u64 r;
    asm("mov.b64 %0, {%1, %2};" : "=l"(r) : "r"(__float_as_uint(x)), "r"(__float_as_uint(y)));
    return r;
}
__device__ __forceinline__ void unpack2(u64 v, float &x, float &y) {
    unsigned a, b;
    asm("mov.b64 {%0, %1}, %2;" : "=r"(a), "=r"(b) : "l"(v));
    x = __uint_as_float(a);
    y = __uint_as_float(b);
}
__device__ __forceinline__ u64 fma2(u64 a, u64 b, u64 c) {   // a*b + c
    u64 d;
    asm("fma.rn.f32x2 %0, %1, %2, %3;" : "=l"(d) : "l"(a), "l"(b), "l"(c));
    return d;
}
__device__ __forceinline__ u64 add2(u64 a, u64 b) {
    u64 d;
    asm("add.rn.f32x2 %0, %1, %2;" : "=l"(d) : "l"(a), "l"(b));
    return d;
}
__device__ __forceinline__ u64 mul2(u64 a, u64 b) {
    u64 d;
    asm("mul.rn.f32x2 %0, %1, %2;" : "=l"(d) : "l"(a), "l"(b));
    return d;
}

// ================= min/max of target (+ one-time per-launch setup) =======
__global__ __launch_bounds__(256) void k_minmax(const float4* __restrict__ t, int n4) {
    if (blockIdx.x == 0 && threadIdx.x == 0) {
        // no race: k_fused (stream-ordered after this kernel) is the only reader
        double w[SWIN], s = 0.0;
        for (int i = 0; i < SWIN; i++) {
            double c = (double)i - (SWIN / 2);
            w[i] = exp(-(c * c) / (2.0 * 1.5 * 1.5));
            s += w[i];
        }
        for (int i = 0; i < SWIN; i++) g_gw[i] = (float)(w[i] / s);
    }
    float lo0 = 3.402823466e38f, hi0 = -3.402823466e38f;
    float lo1 = lo0, hi1 = hi0;
    int stride = gridDim.x * blockDim.x;
    for (int i = blockIdx.x * blockDim.x + threadIdx.x; i < n4; i += 2 * stride) {
        float4 x = t[i];
        lo0 = fminf(lo0, fminf(fminf(x.x, x.y), fminf(x.z, x.w)));
        hi0 = fmaxf(hi0, fmaxf(fmaxf(x.x, x.y), fmaxf(x.z, x.w)));
        int j = i + stride;
        if (j < n4) {
            float4 y = t[j];
            lo1 = fminf(lo1, fminf(fminf(y.x, y.y), fminf(y.z, y.w)));
            hi1 = fmaxf(hi1, fmaxf(fmaxf(y.x, y.y), fmaxf(y.z, y.w)));
        }
    }
    float lo = fminf(lo0, lo1), hi = fmaxf(hi0, hi1);
#pragma unroll
    for (int o = 16; o; o >>= 1) {
        lo = fminf(lo, __shfl_down_sync(0xFFFFFFFFu, lo, o));
        hi = fmaxf(hi, __shfl_down_sync(0xFFFFFFFFu, hi, o));
    }
    if ((threadIdx.x & 31) == 0) {
        atomicMin(&g_minenc, encf(lo));
        atomicMax(&g_maxenc, encf(hi));
    }
}

// ========== fused: MSE + SSIM + sobel + batch-smooth + Pearson + final ====
__global__ __launch_bounds__(256) void k_fused(const float4* __restrict__ o4,
                                               const float4* __restrict__ t4,
                                               float* __restrict__ out,
                                               int out_size, int B) {
    __shared__ u64 uv[IMG_N];            // (u=o+t, v=o-t) packed
    __shared__ u64 gsm[IMG_N];           // sobel (smu, smv) of current image
    __shared__ u64 Huv[IMG_H * HPAD];    // horiz-filtered (U,V)
    __shared__ u64 Hpq[IMG_H * HPAD];    // horiz-filtered (P,Q)
    __shared__ float red[8][7];
    __shared__ int isLast;
    __shared__ double fs[7];

    const int tid = threadIdx.x;
    const int c0 = blockIdx.x * C_IMG;

    // Gaussian weights, symmetric: keep 6, map k -> min(k, 10-k)
    u64 ww[6];
#pragma unroll
    for (int k = 0; k < 6; k++) { float w = g_gw[k]; ww[k] = pack2(w, w); }
    const u64 TWO2 = pack2(2.0f, 2.0f);
    const u64 NEG1 = pack2(-1.0f, -1.0f);

    float R  = decf(g_maxenc) - decf(g_minenc);
    float C1 = (0.01f * R) * (0.01f * R);
    float C2 = (0.03f * R) * (0.03f * R);

    // per-thread accumulators
    float msep = 0.f, ssimp = 0.f;
    float Sa = 0.f, Sb = 0.f, Saa = 0.f, Sbb = 0.f, Sab = 0.f;

    // Pearson batch-recurrence registers: pixels p = tid + 256*k
    u64 gm[4], gc[4];
#pragma unroll
    for (int k = 0; k < 4; k++) { gm[k] = 0; gc[k] = 0; }

#pragma unroll 1
    for (int ii = -1; ii <= C_IMG; ii++) {
        int b = c0 + ii;
        int bc = b < 0 ? 0 : (b >= B ? B - 1 : b);
        const bool interior = (ii >= 0) && (ii < C_IMG);

        // ---------- phase A: load image bc, build uv (+mse if interior)
        if (tid < IMG_N / 4) {
            const float4* ob = o4 + (size_t)bc * (IMG_N / 4);
            const float4* tb = t4 + (size_t)bc * (IMG_N / 4);
            float4 a = ob[tid], c = tb[tid];
            float v0 = a.x - c.x, v1 = a.y - c.y;
            float v2 = a.z - c.z, v3 = a.w - c.w;
            int base = tid * 4;
            uv[base + 0] = pack2(a.x + c.x, v0);
            uv[base + 1] = pack2(a.y + c.y, v1);
            uv[base + 2] = pack2(a.z + c.z, v2);
            uv[base + 3] = pack2(a.w + c.w, v3);
            if (interior)
                msep += v0 * v0 + v1 * v1 + v2 * v2 + v3 * v3;
        }
        __syncthreads();

        // ---------- phase B: horiz conv (tid<168, interior) + sobel (168..223)
        if (tid < 168) {
            if (interior) {
                int r = tid / 6, seg = tid - 6 * (tid / 6);
                int j0 = seg * 3;
                int ibase = r * IMG_W + j0;
                u64 au[3], ap[3];
#pragma unroll
                for (int oi = 0; oi < 3; oi++) { au[oi] = 0; ap[oi] = 0; }
#pragma unroll
                for (int t = 0; t < 13; t++) {
                    u64 xu = uv[ibase + t];
                    u64 xp = mul2(xu, xu);
#pragma unroll
                    for (int oi = 0; oi < 3; oi++) {
                        int k = t - oi;
                        if (k >= 0 && k < SWIN) {
                            int kk = (k < 6) ? k : 10 - k;
                            au[oi] = fma2(ww[kk], xu, au[oi]);
                            ap[oi] = fma2(ww[kk], xp, ap[oi]);
                        }
                    }
                }
                int obase = r * HPAD + j0;
#pragma unroll
                for (int oi = 0; oi < 3; oi++) {
                    Huv[obase + oi] = au[oi];
                    Hpq[obase + oi] = ap[oi];
                }
            }
        } else if (tid < 224) {
            int s = tid - 168;              // 0..55
            int c = s >> 1, half = s & 1;
            int cp = (c < IMG_W - 1) ? c + 1 : IMG_W - 1;
            int cm = (c > 0) ? c - 1 : 0;
            int r0 = half * 14;
            int rm0 = (r0 > 0) ? r0 - 1 : 0;
            u64 dm = fma2(NEG1, uv[rm0 * IMG_W + cm], uv[rm0 * IMG_W + cp]);
            u64 dc = fma2(NEG1, uv[r0 * IMG_W + cm], uv[r0 * IMG_W + cp]);
#pragma unroll
            for (int rr = 0; rr < 14; rr++) {
                int r = r0 + rr;
                int rp = (r < IMG_H - 1) ? r + 1 : IMG_H - 1;
                u64 dp = fma2(NEG1, uv[rp * IMG_W + cm], uv[rp * IMG_W + cp]);
                gsm[r * IMG_W + c] = fma2(TWO2, dc, add2(dm, dp));   // (smu,smv)
                dm = dc; dc = dp;
            }
        }
        __syncthreads();

        // ---------- phase C: vert conv + SSIM (tid<108, interior); Pearson (all)
        if (interior && tid < 108) {
            int cc = tid / 6, seg = tid - 6 * (tid / 6);
            int j0 = seg * 3;
            u64 au[3], ap[3];
#pragma unroll
            for (int oi = 0; oi < 3; oi++) { au[oi] = 0; ap[oi] = 0; }
#pragma unroll
            for (int t = 0; t < 13; t++) {
                u64 xu = Huv[(j0 + t) * HPAD + cc];
                u64 xp = Hpq[(j0 + t) * HPAD + cc];
#pragma unroll
                for (int oi = 0; oi < 3; oi++) {
                    int k = t - oi;
                    if (k >= 0 && k < SWIN) {
                        int kk = (k < 6) ? k : 10 - k;
                        au[oi] = fma2(ww[kk], xu, au[oi]);
                        ap[oi] = fma2(ww[kk], xp, ap[oi]);
                    }
                }
            }
#pragma unroll
            for (int oi = 0; oi < 3; oi++) {
                float U, V, P, Q;
                unpack2(au[oi], U, V);
                unpack2(ap[oi], P, Q);
                float A = U * U, Bv = V * V;
                float num1 = 0.5f * (A - Bv) + C1;           // 2*mu1mu2 + C1
                float den1 = 0.5f * (A + Bv) + C1;           // mu1^2+mu2^2 + C1
                float num2 = 0.5f * (P - Q - A + Bv) + C2;   // 2*s12 + C2
                float den2 = 0.5f * (P + Q - A - Bv) + C2;   // s1+s2 + C2
                ssimp += __fdividef(num1 * num2, den1 * den2);
            }
        }

        // Pearson batch recurrence: s[jp] = g[jp-1] + 2 g[jp] + g[jp+1], jp=ii-1
#pragma unroll
        for (int k = 0; k < 4; k++) {
            int p = tid + k * 256;
            if (p < IMG_N) {
                u64 gn = gsm[p];
                if (ii >= 1) {
                    u64 t1 = fma2(TWO2, gc[k], add2(gm[k], gn));
                    float su, sv;
                    unpack2(t1, su, sv);
                    float sa = su + sv, sb = su - sv;   // scale cancels in pearson
                    Sa += sa; Sb += sb;
                    Saa = fmaf(sa, sa, Saa);
                    Sbb = fmaf(sb, sb, Sbb);
                    Sab = fmaf(sa, sb, Sab);
                }
                gm[k] = gc[k]; gc[k] = gn;
            }
        }
        // no sync needed here: next phase A writes only uv (not read in phase C),
        // and the sync after A orders gsm/Huv rewrites.
    }

    // ---------- block reduction: 7 sums ----------
    float v0 = msep, v1 = ssimp, v2 = Sa, v3 = Sb, v4 = Saa, v5 = Sbb, v6 = Sab;
#pragma unroll
    for (int o = 16; o; o >>= 1) {
        v0 += __shfl_down_sync(0xFFFFFFFFu, v0, o);
        v1 += __shfl_down_sync(0xFFFFFFFFu, v1, o);
        v2 += __shfl_down_sync(0xFFFFFFFFu, v2, o);
        v3 += __shfl_down_sync(0xFFFFFFFFu, v3, o);
        v4 += __shfl_down_sync(0xFFFFFFFFu, v4, o);
        v5 += __shfl_down_sync(0xFFFFFFFFu, v5, o);
        v6 += __shfl_down_sync(0xFFFFFFFFu, v6, o);
    }
    int wid = tid >> 5;
    if ((tid & 31) == 0) {
        red[wid][0] = v0; red[wid][1] = v1; red[wid][2] = v2; red[wid][3] = v3;
        red[wid][4] = v4; red[wid][5] = v5; red[wid][6] = v6;
    }
    __syncthreads();
    if (tid < 7) {
        double s = 0;
        for (int w = 0; w < 8; w++) s += (double)red[w][tid];
        atomicAdd(&g_acc[tid * 64 + (blockIdx.x & 63)], s);
    }

    // ---------- last-block finalize + state reset ----------
    if (tid == 0) {
        __threadfence();
        unsigned prev = atomicAdd(&g_done, 1u);
        isLast = (prev == gridDim.x - 1) ? 1 : 0;
    }
    __syncthreads();
    if (isLast) {
        __threadfence();   // acquire: all blocks' g_acc writes visible
        if (tid < 7) fs[tid] = 0.0;
        __syncthreads();
        for (int i = tid; i < 7 * 64; i += 256) atomicAdd(&fs[i >> 6], g_acc[i]);
        __syncthreads();
        if (tid == 0) {
            double N    = (double)B * (double)IMG_N;
            double mse  = fs[0] / N;
            double ssim = fs[1] / ((double)B * (double)(SOUT * SOUT));
            double psnr = 10.0 * log10(1.0 / mse);
            double SA = fs[2], SB = fs[3], SAA = fs[4], SBB = fs[5], SAB = fs[6];
            double num = SAB - SA * SB / N;
            double den = sqrt((SAA - SA * SA / N) * (SBB - SB * SB / N));
            double epi = num / den;
            double loss = 1.0 * mse + 0.5 * (1.0 - ssim) + 0.1 * epi + 0.01 * psnr;
            for (int i = 0; i < out_size; i++) out[i] = (float)loss;
        }
        // reset persistent state for the next graph replay
        for (int i = tid; i < 7 * 64; i += 256) g_acc[i] = 0.0;
        if (tid == 1) { g_minenc = 0xFFFFFFFFu; g_maxenc = 0u; }
        if (tid == 2) g_done = 0u;
    }
}

// ================= launcher =================
extern "C" void kernel_launch(void* const* d_in, const int* in_sizes, int n_in,
                              void* d_out, int out_size) {
    const float4* o4 = (const float4*)d_in[0];  // "output"
    const float4* t4 = (const float4*)d_in[1];  // "target"
    int n = in_sizes[0];
    int B = n / IMG_N;           // 65536

    k_minmax<<<2048, 256>>>(t4, n / 4);
    k_fused<<<B / C_IMG, 256>>>(o4, t4, (float*)d_out, out_size, B);
}